// round 15
// baseline (speedup 1.0000x reference)
#include <cuda_runtime.h>
#include <cstdint>

#define BATCH 256
#define DLAT  32
#define HID   512
#define GENES 4000
#define NTIL  16
#define USTR  34

__device__ uint4 g_A[2 * 256 * 32 * 32];        // [prec][gtile16][ks][lane]
__device__ uint2 g_B[2 * 256 * 32 * 4 * 32];    // [prec][b][ks][nt][lane]
__device__ uint2 g_Bh[2 * 32 * 32 * 32];        // [prec][btile8][ks][lane]
__device__ float g_pre1[BATCH * HID];
__device__ float g_sc[BATCH * 4096];
__device__ float g_gramPart[(size_t)NTIL * BATCH * DLAT * DLAT];
__device__ float g_loss4[BATCH * 4];

#define FMA2(a, x, y) asm("fma.rn.f32x2 %0, %1, %2, %0;" : "+l"(a) : "l"(x), "l"(y))
#define MMA(d, a, b) \
    asm volatile("mma.sync.aligned.m16n8k16.row.col.f32.bf16.bf16.f32 " \
        "{%0,%1,%2,%3}, {%4,%5,%6,%7}, {%8,%9}, {%0,%1,%2,%3};" \
        : "+f"((d)[0]), "+f"((d)[1]), "+f"((d)[2]), "+f"((d)[3]) \
        : "r"((a).x), "r"((a).y), "r"((a).z), "r"((a).w), "r"((b).x), "r"((b).y))

__device__ __forceinline__ unsigned f2bf(float f) {
    unsigned u = __float_as_uint(f);
    return (u + 0x7FFFu + ((u >> 16) & 1u)) >> 16;
}
__device__ __forceinline__ float bf2f(unsigned h) { return __uint_as_float(h << 16); }
__device__ __forceinline__ unsigned packbf(float a, float b, unsigned& lo) {
    const unsigned ha = f2bf(a), hb = f2bf(b);
    lo = f2bf(a - bf2f(ha)) | (f2bf(b - bf2f(hb)) << 16);
    return ha | (hb << 16);
}

// ---- prep: pre1 for 8 batches + h fragments (fused pre1 + prepH) ----
__global__ void __launch_bounds__(256)
pre1h_kernel(const float* __restrict__ z, const float* __restrict__ W1,
             const float* __restrict__ b1)
{
    __shared__ float sZ[8 * DLAT];
    __shared__ float sh[8 * HID];
    const int bt = blockIdx.x, tid = threadIdx.x;
    sZ[tid] = z[bt * 8 * DLAT + tid];
    __syncthreads();
    #pragma unroll
    for (int half = 0; half < 2; ++half) {
        const int k = tid + half * 256;
        float wv[DLAT];
        #pragma unroll
        for (int i = 0; i < DLAT; ++i) wv[i] = W1[i * HID + k];
        const float bk = b1[k];
        #pragma unroll
        for (int bb = 0; bb < 8; ++bb) {
            float p = bk;
            #pragma unroll
            for (int i = 0; i < DLAT; ++i) p = fmaf(sZ[bb * DLAT + i], wv[i], p);
            g_pre1[(bt * 8 + bb) * HID + k] = p;
            sh[bb * HID + k] = fmaxf(p, 0.0f);
        }
    }
    __syncthreads();
    const int lane = tid & 31, ks8 = tid >> 5;
    const int r = lane >> 2, c = lane & 3;
    #pragma unroll
    for (int kq = 0; kq < 4; ++kq) {
        const int ks = kq * 8 + ks8;
        const int k0 = ks * 16 + 2 * c;
        uint2 hi, lo;
        hi.x = packbf(sh[r * HID + k0],     sh[r * HID + k0 + 1], lo.x);
        hi.y = packbf(sh[r * HID + k0 + 8], sh[r * HID + k0 + 9], lo.y);
        g_Bh[(0 * 32 + bt) * 1024 + ks * 32 + lane] = hi;
        g_Bh[(1 * 32 + bt) * 1024 + ks * 32 + lane] = lo;
    }
}

// ---- prep: A fragments from W2, coalesced (64 genes/block, k-chunked) ----
__global__ void __launch_bounds__(256)
prepA_kernel(const float* __restrict__ W2)
{
    __shared__ float sW2[128 * 65];          // [k-local][g-local(64) pad 65]
    const int gb = blockIdx.x, tid = threadIdx.x;      // gb: 64-gene block
    const int lane = tid & 31, w = tid >> 5;
    const int gt4 = w >> 1;                  // gtile within block (0..3)
    const int ksh = (w & 1) * 4;             // ks-subrange start (0..3 / 4..7)
    const int r = lane >> 2, c = lane & 3;
    #pragma unroll 1
    for (int kc = 0; kc < 4; ++kc) {         // 128 k per chunk
        __syncthreads();
        for (int x = tid; x < 128 * 64; x += 256) {
            const int kl = x >> 6, gl = x & 63;
            const int g = gb * 64 + gl;
            sW2[kl * 65 + gl] = (g < GENES) ? W2[(kc * 128 + kl) * GENES + g] : 0.0f;
        }
        __syncthreads();
        #pragma unroll
        for (int kk = 0; kk < 4; ++kk) {
            const int ksl = ksh + kk;                 // ks within chunk (0..7)
            const int ks  = kc * 8 + ksl;             // global kstep
            const int k0  = ksl * 16 + 2 * c;         // k-local in chunk
            const float* sp = sW2 + gt4 * 16 + r;
            uint4 hi, lo;
            hi.x = packbf(sp[k0 * 65],        sp[(k0 + 1) * 65],       lo.x);
            hi.y = packbf(sp[k0 * 65 + 8],    sp[(k0 + 1) * 65 + 8],   lo.y);
            hi.z = packbf(sp[(k0 + 8) * 65],     sp[(k0 + 9) * 65],     lo.z);
            hi.w = packbf(sp[(k0 + 8) * 65 + 8], sp[(k0 + 9) * 65 + 8], lo.w);
            const int gt = gb * 4 + gt4;
            g_A[(0 * 256 + gt) * 1024 + ks * 32 + lane] = hi;
            g_A[(1 * 256 + gt) * 1024 + ks * 32 + lane] = lo;
        }
    }
}

// ---- prep: B fragments = masked W1; 2 batches per block ----
__global__ void __launch_bounds__(256)
prepB_kernel(const float* __restrict__ W1)
{
    extern __shared__ float sm[];
    float* sW1 = sm;                     // [32][512]
    float* sP  = sm + DLAT * HID;        // [2][512]
    const int b2i = blockIdx.x, tid = threadIdx.x;
    for (int idx = tid; idx < DLAT * HID; idx += 256) sW1[idx] = W1[idx];
    for (int idx = tid; idx < 2 * HID; idx += 256)
        sP[idx] = g_pre1[(b2i * 2) * HID + idx];
    __syncthreads();
    const int lane = tid & 31, ks8 = tid >> 5;
    const int r = lane >> 2, c = lane & 3;
    #pragma unroll
    for (int e = 0; e < 2; ++e) {
        const int b = b2i * 2 + e;
        const float* sPb = sP + e * HID;
        #pragma unroll
        for (int ko = 0; ko < 4; ++ko) {
            const int ks = ko * 8 + ks8, k0 = ks * 16 + 2 * c;
            const bool m0 = sPb[k0] > 0.f, m1 = sPb[k0 + 1] > 0.f;
            const bool m8 = sPb[k0 + 8] > 0.f, m9 = sPb[k0 + 9] > 0.f;
            #pragma unroll
            for (int nt = 0; nt < 4; ++nt) {
                const int n = nt * 8 + r;
                const float v0 = m0 ? sW1[n * HID + k0]     : 0.f;
                const float v1 = m1 ? sW1[n * HID + k0 + 1] : 0.f;
                const float v8 = m8 ? sW1[n * HID + k0 + 8] : 0.f;
                const float v9 = m9 ? sW1[n * HID + k0 + 9] : 0.f;
                uint2 hi, lo;
                hi.x = packbf(v0, v1, lo.x);
                hi.y = packbf(v8, v9, lo.y);
                const int base = ks * 128 + nt * 32 + lane;
                g_B[(0 * 256 + b) * 4096 + base] = hi;
                g_B[(1 * 256 + b) * 4096 + base] = lo;
            }
        }
    }
}

__device__ __forceinline__ float sc_from(float x, float th) {
    const float mu = (x > 0.f) ? (x + log1pf(__expf(-x))) : log1pf(__expf(x));
    const float sg = 1.0f / (1.0f + __expf(-x));
    return sg * sqrtf(th / fmaf(mu, mu + th, 1e-6f));
}

// ---- sc via MMA: pre2[g, 32 batches] + fused weight epilogue ----
__global__ void __launch_bounds__(256)
sc_mma_kernel(const float* __restrict__ b2, const float* __restrict__ lth)
{
    const int tid = threadIdx.x, w = tid >> 5, lane = tid & 31;
    const int gt = blockIdx.x, bg = blockIdx.y;

    const uint4* pA[2][2];
    #pragma unroll
    for (int p = 0; p < 2; ++p)
        #pragma unroll
        for (int m = 0; m < 2; ++m)
            pA[p][m] = g_A + (p * 256 + gt * 16 + w * 2 + m) * 1024 + lane;
    const uint2* pH[2][4];
    #pragma unroll
    for (int p = 0; p < 2; ++p)
        #pragma unroll
        for (int n = 0; n < 4; ++n)
            pH[p][n] = g_Bh + (p * 32 + bg * 4 + n) * 1024 + lane;

    float acc[2][4][4];
    #pragma unroll
    for (int m = 0; m < 2; ++m)
        #pragma unroll
        for (int n = 0; n < 4; ++n)
            #pragma unroll
            for (int e = 0; e < 4; ++e) acc[m][n][e] = 0.0f;

    #pragma unroll 4
    for (int ks = 0; ks < 32; ++ks) {
        uint4 Ab[2][2];
        uint2 Hb[2][4];
        #pragma unroll
        for (int p = 0; p < 2; ++p) {
            #pragma unroll
            for (int m = 0; m < 2; ++m) Ab[p][m] = pA[p][m][ks * 32];
            #pragma unroll
            for (int n = 0; n < 4; ++n) Hb[p][n] = pH[p][n][ks * 32];
        }
        #pragma unroll
        for (int n = 0; n < 4; ++n)
            #pragma unroll
            for (int m = 0; m < 2; ++m) {
                MMA(acc[m][n], Ab[0][m], Hb[0][n]);
                MMA(acc[m][n], Ab[0][m], Hb[1][n]);
                MMA(acc[m][n], Ab[1][m], Hb[0][n]);
            }
    }

    const int r = lane >> 2, c = lane & 3;
    #pragma unroll
    for (int m = 0; m < 2; ++m) {
        const int g0 = gt * 256 + w * 32 + m * 16 + r;
        #pragma unroll
        for (int e2 = 0; e2 < 2; ++e2) {
            const int g = g0 + e2 * 8;
            const bool gok = (g < GENES);
            const float bb2 = gok ? __ldg(b2 + g) : 0.0f;
            const float th  = gok ? __expf(__ldg(lth + g)) : 1.0f;
            #pragma unroll
            for (int n = 0; n < 4; ++n)
                #pragma unroll
                for (int e1 = 0; e1 < 2; ++e1) {
                    const int bb = bg * 32 + n * 8 + 2 * c + e1;
                    const float x = acc[m][n][e2 * 2 + e1] + bb2;
                    g_sc[bb * 4096 + g] = gok ? sc_from(x, th) : 0.0f;
                }
        }
    }
}

// ---- main: warp bf16 MMA (3-term), n=32, sc precomputed ----
__global__ void __launch_bounds__(256, 2)
mma_main()
{
    extern __shared__ float sU[];
    const int tid = threadIdx.x, w = tid >> 5, lane = tid & 31;
    const int b = blockIdx.x, tile = blockIdx.y;

    const uint4* pA[2][2];
    #pragma unroll
    for (int p = 0; p < 2; ++p)
        #pragma unroll
        for (int m = 0; m < 2; ++m)
            pA[p][m] = g_A + (p * 256 + tile * 16 + w * 2 + m) * 1024 + lane;
    const uint2* pB[2];
    #pragma unroll
    for (int p = 0; p < 2; ++p) pB[p] = g_B + (p * 256 + b) * 4096 + lane;

    float acc[2][4][4];
    #pragma unroll
    for (int m = 0; m < 2; ++m)
        #pragma unroll
        for (int n = 0; n < 4; ++n)
            #pragma unroll
            for (int e = 0; e < 4; ++e) acc[m][n][e] = 0.0f;

    uint4 Ab[2][2][2];
    uint2 Bb[2][2][4];
    #pragma unroll
    for (int p = 0; p < 2; ++p) {
        #pragma unroll
        for (int m = 0; m < 2; ++m) Ab[0][p][m] = pA[p][m][0];
        #pragma unroll
        for (int n = 0; n < 4; ++n) Bb[0][p][n] = pB[p][n * 32];
    }

    #pragma unroll 8
    for (int ks = 0; ks < 32; ++ks) {
        const int cur = ks & 1, nxt = cur ^ 1;
        const int ksn = (ks < 31) ? ks + 1 : 31;
        #pragma unroll
        for (int p = 0; p < 2; ++p) {
            #pragma unroll
            for (int m = 0; m < 2; ++m) Ab[nxt][p][m] = pA[p][m][ksn * 32];
            #pragma unroll
            for (int n = 0; n < 4; ++n)
                Bb[nxt][p][n] = pB[p][ksn * 128 + n * 32];
        }
        #pragma unroll
        for (int n = 0; n < 4; ++n)
            #pragma unroll
            for (int m = 0; m < 2; ++m) {
                MMA(acc[m][n], Ab[cur][0][m], Bb[cur][0][n]);
                MMA(acc[m][n], Ab[cur][0][m], Bb[cur][1][n]);
                MMA(acc[m][n], Ab[cur][1][m], Bb[cur][0][n]);
            }
    }

    // epilogue: U = sc * V into smem
    const int r = lane >> 2, c2 = (lane & 3) * 2;
    const float* scb = g_sc + b * 4096 + tile * 256 + w * 32;
    #pragma unroll
    for (int m = 0; m < 2; ++m) {
        const float sc0 = __ldg(scb + m * 16 + r);
        const float sc1 = __ldg(scb + m * 16 + r + 8);
        float* u0 = sU + (w * 32 + m * 16 + r) * USTR;
        float* u1 = u0 + 8 * USTR;
        #pragma unroll
        for (int n = 0; n < 4; ++n) {
            *reinterpret_cast<float2*>(u0 + n * 8 + c2) =
                make_float2(acc[m][n][0] * sc0, acc[m][n][1] * sc0);
            *reinterpret_cast<float2*>(u1 + n * 8 + c2) =
                make_float2(acc[m][n][2] * sc1, acc[m][n][3] * sc1);
        }
    }
    __syncthreads();

    // SYRK: Gram partial = U^T U
    const int ti = tid & 15, tj = tid >> 4;
    {
        const float* pa = sU + 2 * ti;
        const float* pq = sU + 2 * tj;
        unsigned long long ga0 = 0ULL, ga1 = 0ULL;
        #pragma unroll 4
        for (int rI = 0; rI < 256; ++rI) {
            const unsigned long long av =
                *reinterpret_cast<const unsigned long long*>(pa + rI * USTR);
            const unsigned long long bv =
                *reinterpret_cast<const unsigned long long*>(pq + rI * USTR);
            unsigned alo, ahi;
            asm("mov.b64 {%0,%1}, %2;" : "=r"(alo), "=r"(ahi) : "l"(av));
            unsigned long long ad0, ad1;
            asm("mov.b64 %0, {%1,%1};" : "=l"(ad0) : "r"(alo));
            asm("mov.b64 %0, {%1,%1};" : "=l"(ad1) : "r"(ahi));
            FMA2(ga0, ad0, bv);
            FMA2(ga1, ad1, bv);
        }
        float* dst = g_gramPart + ((size_t)tile * BATCH + b) * 1024;
        unsigned l0, h0, l1, h1;
        asm("mov.b64 {%0,%1}, %2;" : "=r"(l0), "=r"(h0) : "l"(ga0));
        asm("mov.b64 {%0,%1}, %2;" : "=r"(l1), "=r"(h1) : "l"(ga1));
        dst[(2*ti)   * 32 + 2*tj    ] = __uint_as_float(l0);
        dst[(2*ti)   * 32 + 2*tj + 1] = __uint_as_float(h0);
        dst[(2*ti+1) * 32 + 2*tj    ] = __uint_as_float(l1);
        dst[(2*ti+1) * 32 + 2*tj + 1] = __uint_as_float(h1);
    }
}

// ---- loss: grid (256 b, 4 quarters), then final reduce ----
__global__ void __launch_bounds__(256)
loss_part_kernel()
{
    const int b = blockIdx.x, q = blockIdx.y, t = threadIdx.x;
    const int ij = q * 256 + t;
    float s = 0.0f;
    #pragma unroll
    for (int cc = 0; cc < NTIL; ++cc)
        s += g_gramPart[((size_t)cc * BATCH + b) * 1024 + ij];
    if (ij % 33 == 0) s -= 1.0f;
    float v = s * s;
    __shared__ float red[256];
    red[t] = v;
    __syncthreads();
    for (int o = 128; o > 0; o >>= 1) {
        if (t < o) red[t] += red[t + o];
        __syncthreads();
    }
    if (t == 0) g_loss4[b * 4 + q] = red[0];
}

__global__ void __launch_bounds__(256)
final_reduce_kernel(float* __restrict__ out)
{
    const int t = threadIdx.x;
    const float4 v = *reinterpret_cast<const float4*>(g_loss4 + t * 4);
    __shared__ float red[256];
    red[t] = v.x + v.y + v.z + v.w;
    __syncthreads();
    for (int o = 128; o > 0; o >>= 1) {
        if (t < o) red[t] += red[t + o];
        __syncthreads();
    }
    if (t == 0) out[0] = red[0] * (1.0f / (float)BATCH);
}

extern "C" void kernel_launch(void* const* d_in, const int* in_sizes, int n_in,
                              void* d_out, int out_size)
{
    const float* z   = (const float*)d_in[0];
    const float* W1  = (const float*)d_in[1];
    const float* b1  = (const float*)d_in[2];
    const float* W2  = (const float*)d_in[3];
    const float* b2  = (const float*)d_in[4];
    const float* lth = (const float*)d_in[5];

    pre1h_kernel<<<32, 256>>>(z, W1, b1);
    prepA_kernel<<<64, 256>>>(W2);

    const int smBsz = (DLAT * HID + 2 * HID) * sizeof(float);   // 69,632
    cudaFuncSetAttribute(prepB_kernel, cudaFuncAttributeMaxDynamicSharedMemorySize, smBsz);
    prepB_kernel<<<BATCH / 2, 256, smBsz>>>(W1);
    sc_mma_kernel<<<dim3(16, 8), 256>>>(b2, lth);

    const int smU = 256 * USTR * sizeof(float);
    cudaFuncSetAttribute(mma_main, cudaFuncAttributeMaxDynamicSharedMemorySize, smU);
    mma_main<<<dim3(BATCH, NTIL), 256, smU>>>();

    loss_part_kernel<<<dim3(BATCH, 4), 256>>>();
    final_reduce_kernel<<<1, 256>>>((float*)d_out);
}

// round 16
// speedup vs baseline: 1.0261x; 1.0261x over previous
#include <cuda_runtime.h>
#include <cstdint>

#define BATCH 256
#define DLAT  32
#define HID   512
#define GENES 4000
#define NTIL  16
#define USTR  34

__device__ uint4 g_A[2 * 256 * 32 * 32];        // [prec][gtile16][ks][lane]
__device__ uint2 g_B[2 * 256 * 32 * 4 * 32];    // [prec][b][ks][nt][lane]
__device__ uint2 g_Bh[2 * 32 * 32 * 32];        // [prec][btile8][ks][lane]
__device__ float g_pre1[BATCH * HID];
__device__ float g_sc[BATCH * 4096];
__device__ float g_gramPart[(size_t)NTIL * BATCH * DLAT * DLAT];
__device__ float g_lossb[BATCH];

#define FMA2(a, x, y) asm("fma.rn.f32x2 %0, %1, %2, %0;" : "+l"(a) : "l"(x), "l"(y))
#define MMA(d, a, b) \
    asm volatile("mma.sync.aligned.m16n8k16.row.col.f32.bf16.bf16.f32 " \
        "{%0,%1,%2,%3}, {%4,%5,%6,%7}, {%8,%9}, {%0,%1,%2,%3};" \
        : "+f"((d)[0]), "+f"((d)[1]), "+f"((d)[2]), "+f"((d)[3]) \
        : "r"((a).x), "r"((a).y), "r"((a).z), "r"((a).w), "r"((b).x), "r"((b).y))

__device__ __forceinline__ unsigned f2bf(float f) {
    unsigned u = __float_as_uint(f);
    return (u + 0x7FFFu + ((u >> 16) & 1u)) >> 16;
}
__device__ __forceinline__ float bf2f(unsigned h) { return __uint_as_float(h << 16); }
__device__ __forceinline__ unsigned packbf(float a, float b, unsigned& lo) {
    const unsigned ha = f2bf(a), hb = f2bf(b);
    lo = f2bf(a - bf2f(ha)) | (f2bf(b - bf2f(hb)) << 16);
    return ha | (hb << 16);
}

// ---- prep: pre1[b][k] ----
__global__ void __launch_bounds__(256)
pre1_kernel(const float* __restrict__ z, const float* __restrict__ W1,
            const float* __restrict__ b1)
{
    __shared__ float sZ[DLAT];
    const int b = blockIdx.x, tid = threadIdx.x;
    if (tid < DLAT) sZ[tid] = z[b * DLAT + tid];
    __syncthreads();
    #pragma unroll
    for (int kk = 0; kk < 2; ++kk) {
        const int k = tid + kk * 256;
        float acc = b1[k];
        #pragma unroll
        for (int i = 0; i < DLAT; ++i) acc = fmaf(sZ[i], W1[i * HID + k], acc);
        g_pre1[b * HID + k] = acc;
    }
}

// ---- prep: A fragments from W2 ----
__global__ void __launch_bounds__(256)
prepA_kernel(const float* __restrict__ W2)
{
    __shared__ float sW2[HID * 16];
    const int gt = blockIdx.x, tid = threadIdx.x;
    for (int idx = tid; idx < HID * 16; idx += 256) {
        const int k = idx >> 4, gl = idx & 15, g = gt * 16 + gl;
        sW2[idx] = (g < GENES) ? W2[k * GENES + g] : 0.0f;
    }
    __syncthreads();
    const int lane = tid & 31, ks8 = tid >> 5;
    const int r = lane >> 2, c = lane & 3;
    #pragma unroll
    for (int ko = 0; ko < 4; ++ko) {
        const int ks = ko * 8 + ks8, k0 = ks * 16 + 2 * c;
        uint4 hi, lo;
        hi.x = packbf(sW2[k0 * 16 + r],       sW2[(k0 + 1) * 16 + r],       lo.x);
        hi.y = packbf(sW2[k0 * 16 + r + 8],   sW2[(k0 + 1) * 16 + r + 8],   lo.y);
        hi.z = packbf(sW2[(k0 + 8) * 16 + r],     sW2[(k0 + 9) * 16 + r],     lo.z);
        hi.w = packbf(sW2[(k0 + 8) * 16 + r + 8], sW2[(k0 + 9) * 16 + r + 8], lo.w);
        g_A[(0 * 256 + gt) * 1024 + ks * 32 + lane] = hi;
        g_A[(1 * 256 + gt) * 1024 + ks * 32 + lane] = lo;
    }
}

// ---- prep: B fragments = masked W1; 2 batches per block ----
__global__ void __launch_bounds__(256)
prepB_kernel(const float* __restrict__ W1)
{
    extern __shared__ float sm[];
    float* sW1 = sm;                     // [32][512]
    float* sP  = sm + DLAT * HID;        // [2][512]
    const int b2i = blockIdx.x, tid = threadIdx.x;
    for (int idx = tid; idx < DLAT * HID; idx += 256) sW1[idx] = W1[idx];
    for (int idx = tid; idx < 2 * HID; idx += 256)
        sP[idx] = g_pre1[(b2i * 2) * HID + idx];
    __syncthreads();
    const int lane = tid & 31, ks8 = tid >> 5;
    const int r = lane >> 2, c = lane & 3;
    #pragma unroll
    for (int e = 0; e < 2; ++e) {
        const int b = b2i * 2 + e;
        const float* sPb = sP + e * HID;
        #pragma unroll
        for (int ko = 0; ko < 4; ++ko) {
            const int ks = ko * 8 + ks8, k0 = ks * 16 + 2 * c;
            const bool m0 = sPb[k0] > 0.f, m1 = sPb[k0 + 1] > 0.f;
            const bool m8 = sPb[k0 + 8] > 0.f, m9 = sPb[k0 + 9] > 0.f;
            #pragma unroll
            for (int nt = 0; nt < 4; ++nt) {
                const int n = nt * 8 + r;
                const float v0 = m0 ? sW1[n * HID + k0]     : 0.f;
                const float v1 = m1 ? sW1[n * HID + k0 + 1] : 0.f;
                const float v8 = m8 ? sW1[n * HID + k0 + 8] : 0.f;
                const float v9 = m9 ? sW1[n * HID + k0 + 9] : 0.f;
                uint2 hi, lo;
                hi.x = packbf(v0, v1, lo.x);
                hi.y = packbf(v8, v9, lo.y);
                const int base = ks * 128 + nt * 32 + lane;
                g_B[(0 * 256 + b) * 4096 + base] = hi;
                g_B[(1 * 256 + b) * 4096 + base] = lo;
            }
        }
    }
}

// ---- prep: h fragments, k-range split grid (32, 4) ----
__global__ void __launch_bounds__(256)
prepH_kernel()
{
    __shared__ float sh[8 * 128];
    const int bt = blockIdx.x, kq = blockIdx.y, tid = threadIdx.x;
    for (int idx = tid; idx < 8 * 128; idx += 256) {
        const int bb = idx >> 7, kl = idx & 127;
        sh[bb * 128 + kl] = fmaxf(g_pre1[(bt * 8 + bb) * HID + kq * 128 + kl], 0.0f);
    }
    __syncthreads();
    const int lane = tid & 31, ks8 = tid >> 5;
    const int ks = kq * 8 + ks8;
    const int r = lane >> 2, c = lane & 3;
    const int k0 = ks8 * 16 + 2 * c;
    uint2 hi, lo;
    hi.x = packbf(sh[r * 128 + k0],     sh[r * 128 + k0 + 1], lo.x);
    hi.y = packbf(sh[r * 128 + k0 + 8], sh[r * 128 + k0 + 9], lo.y);
    g_Bh[(0 * 32 + bt) * 1024 + ks * 32 + lane] = hi;
    g_Bh[(1 * 32 + bt) * 1024 + ks * 32 + lane] = lo;
}

__device__ __forceinline__ float sc_from(float x, float th) {
    const float mu = (x > 0.f) ? (x + log1pf(__expf(-x))) : log1pf(__expf(x));
    const float sg = 1.0f / (1.0f + __expf(-x));
    return sg * sqrtf(th / fmaf(mu, mu + th, 1e-6f));
}

// ---- sc via MMA with register double-buffer (pipelined) ----
__global__ void __launch_bounds__(256)
sc_mma_kernel(const float* __restrict__ b2, const float* __restrict__ lth)
{
    const int tid = threadIdx.x, w = tid >> 5, lane = tid & 31;
    const int gt = blockIdx.x, bg = blockIdx.y;

    const uint4* pA[2][2];
    #pragma unroll
    for (int p = 0; p < 2; ++p)
        #pragma unroll
        for (int m = 0; m < 2; ++m)
            pA[p][m] = g_A + (p * 256 + gt * 16 + w * 2 + m) * 1024 + lane;
    const uint2* pH[2][4];
    #pragma unroll
    for (int p = 0; p < 2; ++p)
        #pragma unroll
        for (int n = 0; n < 4; ++n)
            pH[p][n] = g_Bh + (p * 32 + bg * 4 + n) * 1024 + lane;

    float acc[2][4][4];
    #pragma unroll
    for (int m = 0; m < 2; ++m)
        #pragma unroll
        for (int n = 0; n < 4; ++n)
            #pragma unroll
            for (int e = 0; e < 4; ++e) acc[m][n][e] = 0.0f;

    uint4 Ab[2][2][2];          // [stage][prec][m]
    uint2 Hb[2][2][4];          // [stage][prec][n]
    #pragma unroll
    for (int p = 0; p < 2; ++p) {
        #pragma unroll
        for (int m = 0; m < 2; ++m) Ab[0][p][m] = pA[p][m][0];
        #pragma unroll
        for (int n = 0; n < 4; ++n) Hb[0][p][n] = pH[p][n][0];
    }

    #pragma unroll 8
    for (int ks = 0; ks < 32; ++ks) {
        const int cur = ks & 1, nxt = cur ^ 1;
        const int ksn = (ks < 31) ? ks + 1 : 31;
        #pragma unroll
        for (int p = 0; p < 2; ++p) {
            #pragma unroll
            for (int m = 0; m < 2; ++m) Ab[nxt][p][m] = pA[p][m][ksn * 32];
            #pragma unroll
            for (int n = 0; n < 4; ++n) Hb[nxt][p][n] = pH[p][n][ksn * 32];
        }
        #pragma unroll
        for (int n = 0; n < 4; ++n)
            #pragma unroll
            for (int m = 0; m < 2; ++m) {
                MMA(acc[m][n], Ab[cur][0][m], Hb[cur][0][n]);
                MMA(acc[m][n], Ab[cur][0][m], Hb[cur][1][n]);
                MMA(acc[m][n], Ab[cur][1][m], Hb[cur][0][n]);
            }
    }

    const int r = lane >> 2, c = lane & 3;
    #pragma unroll
    for (int m = 0; m < 2; ++m) {
        const int g0 = gt * 256 + w * 32 + m * 16 + r;
        #pragma unroll
        for (int e2 = 0; e2 < 2; ++e2) {
            const int g = g0 + e2 * 8;
            const bool gok = (g < GENES);
            const float bb2 = gok ? __ldg(b2 + g) : 0.0f;
            const float th  = gok ? __expf(__ldg(lth + g)) : 1.0f;
            #pragma unroll
            for (int n = 0; n < 4; ++n)
                #pragma unroll
                for (int e1 = 0; e1 < 2; ++e1) {
                    const int bb = bg * 32 + n * 8 + 2 * c + e1;
                    const float x = acc[m][n][e2 * 2 + e1] + bb2;
                    g_sc[bb * 4096 + g] = gok ? sc_from(x, th) : 0.0f;
                }
        }
    }
}

// ---- main: warp bf16 MMA (3-term), n=32, sc precomputed ----
__global__ void __launch_bounds__(256, 2)
mma_main()
{
    extern __shared__ float sU[];
    const int tid = threadIdx.x, w = tid >> 5, lane = tid & 31;
    const int b = blockIdx.x, tile = blockIdx.y;

    const uint4* pA[2][2];
    #pragma unroll
    for (int p = 0; p < 2; ++p)
        #pragma unroll
        for (int m = 0; m < 2; ++m)
            pA[p][m] = g_A + (p * 256 + tile * 16 + w * 2 + m) * 1024 + lane;
    const uint2* pB[2];
    #pragma unroll
    for (int p = 0; p < 2; ++p) pB[p] = g_B + (p * 256 + b) * 4096 + lane;

    float acc[2][4][4];
    #pragma unroll
    for (int m = 0; m < 2; ++m)
        #pragma unroll
        for (int n = 0; n < 4; ++n)
            #pragma unroll
            for (int e = 0; e < 4; ++e) acc[m][n][e] = 0.0f;

    uint4 Ab[2][2][2];
    uint2 Bb[2][2][4];
    #pragma unroll
    for (int p = 0; p < 2; ++p) {
        #pragma unroll
        for (int m = 0; m < 2; ++m) Ab[0][p][m] = pA[p][m][0];
        #pragma unroll
        for (int n = 0; n < 4; ++n) Bb[0][p][n] = pB[p][n * 32];
    }

    #pragma unroll 8
    for (int ks = 0; ks < 32; ++ks) {
        const int cur = ks & 1, nxt = cur ^ 1;
        const int ksn = (ks < 31) ? ks + 1 : 31;
        #pragma unroll
        for (int p = 0; p < 2; ++p) {
            #pragma unroll
            for (int m = 0; m < 2; ++m) Ab[nxt][p][m] = pA[p][m][ksn * 32];
            #pragma unroll
            for (int n = 0; n < 4; ++n)
                Bb[nxt][p][n] = pB[p][ksn * 128 + n * 32];
        }
        #pragma unroll
        for (int n = 0; n < 4; ++n)
            #pragma unroll
            for (int m = 0; m < 2; ++m) {
                MMA(acc[m][n], Ab[cur][0][m], Bb[cur][0][n]);
                MMA(acc[m][n], Ab[cur][0][m], Bb[cur][1][n]);
                MMA(acc[m][n], Ab[cur][1][m], Bb[cur][0][n]);
            }
    }

    // epilogue: U = sc * V into smem
    const int r = lane >> 2, c2 = (lane & 3) * 2;
    const float* scb = g_sc + b * 4096 + tile * 256 + w * 32;
    #pragma unroll
    for (int m = 0; m < 2; ++m) {
        const float sc0 = __ldg(scb + m * 16 + r);
        const float sc1 = __ldg(scb + m * 16 + r + 8);
        float* u0 = sU + (w * 32 + m * 16 + r) * USTR;
        float* u1 = u0 + 8 * USTR;
        #pragma unroll
        for (int n = 0; n < 4; ++n) {
            *reinterpret_cast<float2*>(u0 + n * 8 + c2) =
                make_float2(acc[m][n][0] * sc0, acc[m][n][1] * sc0);
            *reinterpret_cast<float2*>(u1 + n * 8 + c2) =
                make_float2(acc[m][n][2] * sc1, acc[m][n][3] * sc1);
        }
    }
    __syncthreads();

    // SYRK: Gram partial = U^T U
    const int ti = tid & 15, tj = tid >> 4;
    {
        const float* pa = sU + 2 * ti;
        const float* pq = sU + 2 * tj;
        unsigned long long ga0 = 0ULL, ga1 = 0ULL;
        #pragma unroll 4
        for (int rI = 0; rI < 256; ++rI) {
            const unsigned long long av =
                *reinterpret_cast<const unsigned long long*>(pa + rI * USTR);
            const unsigned long long bv =
                *reinterpret_cast<const unsigned long long*>(pq + rI * USTR);
            unsigned alo, ahi;
            asm("mov.b64 {%0,%1}, %2;" : "=r"(alo), "=r"(ahi) : "l"(av));
            unsigned long long ad0, ad1;
            asm("mov.b64 %0, {%1,%1};" : "=l"(ad0) : "r"(alo));
            asm("mov.b64 %0, {%1,%1};" : "=l"(ad1) : "r"(ahi));
            FMA2(ga0, ad0, bv);
            FMA2(ga1, ad1, bv);
        }
        float* dst = g_gramPart + ((size_t)tile * BATCH + b) * 1024;
        unsigned l0, h0, l1, h1;
        asm("mov.b64 {%0,%1}, %2;" : "=r"(l0), "=r"(h0) : "l"(ga0));
        asm("mov.b64 {%0,%1}, %2;" : "=r"(l1), "=r"(h1) : "l"(ga1));
        dst[(2*ti)   * 32 + 2*tj    ] = __uint_as_float(l0);
        dst[(2*ti)   * 32 + 2*tj + 1] = __uint_as_float(h0);
        dst[(2*ti+1) * 32 + 2*tj    ] = __uint_as_float(l1);
        dst[(2*ti+1) * 32 + 2*tj + 1] = __uint_as_float(h1);
    }
}

__global__ void __launch_bounds__(256)
loss_per_b_kernel()
{
    const int b = blockIdx.x, t = threadIdx.x;
    float accl = 0.0f;
    #pragma unroll
    for (int rr = 0; rr < 4; ++rr) {
        const int ij = t + rr * 256;
        float s = 0.0f;
        for (int cc = 0; cc < NTIL; ++cc)
            s += g_gramPart[((size_t)cc * BATCH + b) * 1024 + ij];
        if (ij % 33 == 0) s -= 1.0f;
        accl = fmaf(s, s, accl);
    }
    __shared__ float red[256];
    red[t] = accl;
    __syncthreads();
    for (int o = 128; o > 0; o >>= 1) {
        if (t < o) red[t] += red[t + o];
        __syncthreads();
    }
    if (t == 0) g_lossb[b] = red[0];
}

__global__ void __launch_bounds__(256)
final_reduce_kernel(float* __restrict__ out)
{
    const int t = threadIdx.x;
    __shared__ float red[256];
    red[t] = g_lossb[t];
    __syncthreads();
    for (int o = 128; o > 0; o >>= 1) {
        if (t < o) red[t] += red[t + o];
        __syncthreads();
    }
    if (t == 0) out[0] = red[0] * (1.0f / (float)BATCH);
}

extern "C" void kernel_launch(void* const* d_in, const int* in_sizes, int n_in,
                              void* d_out, int out_size)
{
    const float* z   = (const float*)d_in[0];
    const float* W1  = (const float*)d_in[1];
    const float* b1  = (const float*)d_in[2];
    const float* W2  = (const float*)d_in[3];
    const float* b2  = (const float*)d_in[4];
    const float* lth = (const float*)d_in[5];

    pre1_kernel<<<BATCH, 256>>>(z, W1, b1);
    prepA_kernel<<<256, 256>>>(W2);

    const int smBsz = (DLAT * HID + 2 * HID) * sizeof(float);   // 69,632
    cudaFuncSetAttribute(prepB_kernel, cudaFuncAttributeMaxDynamicSharedMemorySize, smBsz);
    prepB_kernel<<<BATCH / 2, 256, smBsz>>>(W1);
    prepH_kernel<<<dim3(32, 4), 256>>>();
    sc_mma_kernel<<<dim3(16, 8), 256>>>(b2, lth);

    const int smU = 256 * USTR * sizeof(float);
    cudaFuncSetAttribute(mma_main, cudaFuncAttributeMaxDynamicSharedMemorySize, smU);
    mma_main<<<dim3(BATCH, NTIL), 256, smU>>>();

    loss_per_b_kernel<<<BATCH, 256>>>();
    final_reduce_kernel<<<1, 256>>>((float*)d_out);
}

// round 17
// speedup vs baseline: 1.1786x; 1.1486x over previous
#include <cuda_runtime.h>
#include <cuda_fp16.h>
#include <cstdint>

#define BATCH 256
#define DLAT  32
#define HID   512
#define GENES 4000
#define NTIL  16
#define USTR  34

__device__ uint4 g_A[2 * 256 * 32 * 32];        // [prec][gtile16][ks][lane] fp16
__device__ uint2 g_B[(size_t)256 * 32 * 4 * 32];// [b][ks][nt][lane] fp16 hi only
__device__ uint2 g_Bh[2 * 32 * 32 * 32];        // [prec][btile8][ks][lane] fp16
__device__ float g_pre1[BATCH * HID];
__device__ float g_sc[BATCH * 4096];
__device__ float g_gramPart[(size_t)NTIL * BATCH * DLAT * DLAT];
__device__ float g_lossb[BATCH];

#define FMA2(a, x, y) asm("fma.rn.f32x2 %0, %1, %2, %0;" : "+l"(a) : "l"(x), "l"(y))
#define MMA(d, a, b) \
    asm volatile("mma.sync.aligned.m16n8k16.row.col.f32.f16.f16.f32 " \
        "{%0,%1,%2,%3}, {%4,%5,%6,%7}, {%8,%9}, {%0,%1,%2,%3};" \
        : "+f"((d)[0]), "+f"((d)[1]), "+f"((d)[2]), "+f"((d)[3]) \
        : "r"((a).x), "r"((a).y), "r"((a).z), "r"((a).w), "r"((b).x), "r"((b).y))

__device__ __forceinline__ unsigned packh(float a, float b, unsigned& lo) {
    const __half ha = __float2half_rn(a), hb = __float2half_rn(b);
    const __half la = __float2half_rn(a - __half2float(ha));
    const __half lb = __float2half_rn(b - __half2float(hb));
    lo = (unsigned)__half_as_ushort(la) | ((unsigned)__half_as_ushort(lb) << 16);
    return (unsigned)__half_as_ushort(ha) | ((unsigned)__half_as_ushort(hb) << 16);
}
__device__ __forceinline__ unsigned packh1(float a, float b) {
    return (unsigned)__half_as_ushort(__float2half_rn(a)) |
           ((unsigned)__half_as_ushort(__float2half_rn(b)) << 16);
}

// ---- prep: pre1[b][k] ----
__global__ void __launch_bounds__(256)
pre1_kernel(const float* __restrict__ z, const float* __restrict__ W1,
            const float* __restrict__ b1)
{
    __shared__ float sZ[DLAT];
    const int b = blockIdx.x, tid = threadIdx.x;
    if (tid < DLAT) sZ[tid] = z[b * DLAT + tid];
    __syncthreads();
    #pragma unroll
    for (int kk = 0; kk < 2; ++kk) {
        const int k = tid + kk * 256;
        float acc = b1[k];
        #pragma unroll
        for (int i = 0; i < DLAT; ++i) acc = fmaf(sZ[i], W1[i * HID + k], acc);
        g_pre1[b * HID + k] = acc;
    }
}

// ---- prep: A fragments from W2 (fp16 hi/lo) ----
__global__ void __launch_bounds__(256)
prepA_kernel(const float* __restrict__ W2)
{
    __shared__ float sW2[HID * 16];
    const int gt = blockIdx.x, tid = threadIdx.x;
    for (int idx = tid; idx < HID * 16; idx += 256) {
        const int k = idx >> 4, gl = idx & 15, g = gt * 16 + gl;
        sW2[idx] = (g < GENES) ? W2[k * GENES + g] : 0.0f;
    }
    __syncthreads();
    const int lane = tid & 31, ks8 = tid >> 5;
    const int r = lane >> 2, c = lane & 3;
    #pragma unroll
    for (int ko = 0; ko < 4; ++ko) {
        const int ks = ko * 8 + ks8, k0 = ks * 16 + 2 * c;
        uint4 hi, lo;
        hi.x = packh(sW2[k0 * 16 + r],       sW2[(k0 + 1) * 16 + r],       lo.x);
        hi.y = packh(sW2[k0 * 16 + r + 8],   sW2[(k0 + 1) * 16 + r + 8],   lo.y);
        hi.z = packh(sW2[(k0 + 8) * 16 + r],     sW2[(k0 + 9) * 16 + r],     lo.z);
        hi.w = packh(sW2[(k0 + 8) * 16 + r + 8], sW2[(k0 + 9) * 16 + r + 8], lo.w);
        g_A[(0 * 256 + gt) * 1024 + ks * 32 + lane] = hi;
        g_A[(1 * 256 + gt) * 1024 + ks * 32 + lane] = lo;
    }
}

// ---- prep: B fragments = masked W1, fp16 hi only; 2 batches/block ----
__global__ void __launch_bounds__(256)
prepB_kernel(const float* __restrict__ W1)
{
    extern __shared__ float sm[];
    float* sW1 = sm;                     // [32][512]
    float* sP  = sm + DLAT * HID;        // [2][512]
    const int b2i = blockIdx.x, tid = threadIdx.x;
    for (int idx = tid; idx < DLAT * HID; idx += 256) sW1[idx] = W1[idx];
    for (int idx = tid; idx < 2 * HID; idx += 256)
        sP[idx] = g_pre1[(b2i * 2) * HID + idx];
    __syncthreads();
    const int lane = tid & 31, ks8 = tid >> 5;
    const int r = lane >> 2, c = lane & 3;
    #pragma unroll
    for (int e = 0; e < 2; ++e) {
        const int b = b2i * 2 + e;
        const float* sPb = sP + e * HID;
        #pragma unroll
        for (int ko = 0; ko < 4; ++ko) {
            const int ks = ko * 8 + ks8, k0 = ks * 16 + 2 * c;
            const bool m0 = sPb[k0] > 0.f, m1 = sPb[k0 + 1] > 0.f;
            const bool m8 = sPb[k0 + 8] > 0.f, m9 = sPb[k0 + 9] > 0.f;
            #pragma unroll
            for (int nt = 0; nt < 4; ++nt) {
                const int n = nt * 8 + r;
                uint2 hi;
                hi.x = packh1(m0 ? sW1[n * HID + k0]     : 0.f,
                              m1 ? sW1[n * HID + k0 + 1] : 0.f);
                hi.y = packh1(m8 ? sW1[n * HID + k0 + 8] : 0.f,
                              m9 ? sW1[n * HID + k0 + 9] : 0.f);
                g_B[(size_t)b * 4096 + ks * 128 + nt * 32 + lane] = hi;
            }
        }
    }
}

// ---- prep: h fragments (fp16 hi/lo), grid (32, 4) ----
__global__ void __launch_bounds__(256)
prepH_kernel()
{
    __shared__ float sh[8 * 128];
    const int bt = blockIdx.x, kq = blockIdx.y, tid = threadIdx.x;
    for (int idx = tid; idx < 8 * 128; idx += 256) {
        const int bb = idx >> 7, kl = idx & 127;
        sh[bb * 128 + kl] = fmaxf(g_pre1[(bt * 8 + bb) * HID + kq * 128 + kl], 0.0f);
    }
    __syncthreads();
    const int lane = tid & 31, ks8 = tid >> 5;
    const int ks = kq * 8 + ks8;
    const int r = lane >> 2, c = lane & 3;
    const int k0 = ks8 * 16 + 2 * c;
    uint2 hi, lo;
    hi.x = packh(sh[r * 128 + k0],     sh[r * 128 + k0 + 1], lo.x);
    hi.y = packh(sh[r * 128 + k0 + 8], sh[r * 128 + k0 + 9], lo.y);
    g_Bh[(0 * 32 + bt) * 1024 + ks * 32 + lane] = hi;
    g_Bh[(1 * 32 + bt) * 1024 + ks * 32 + lane] = lo;
}

__device__ __forceinline__ float sc_from(float x, float th) {
    const float mu = (x > 0.f) ? (x + log1pf(__expf(-x))) : log1pf(__expf(x));
    const float sg = 1.0f / (1.0f + __expf(-x));
    return sg * sqrtf(th / fmaf(mu, mu + th, 1e-6f));
}

// ---- sc via MMA (3 fp16 MMAs, pipelined) ----
__global__ void __launch_bounds__(256)
sc_mma_kernel(const float* __restrict__ b2, const float* __restrict__ lth)
{
    const int tid = threadIdx.x, w = tid >> 5, lane = tid & 31;
    const int gt = blockIdx.x, bg = blockIdx.y;

    const uint4* pA[2][2];
    #pragma unroll
    for (int p = 0; p < 2; ++p)
        #pragma unroll
        for (int m = 0; m < 2; ++m)
            pA[p][m] = g_A + (p * 256 + gt * 16 + w * 2 + m) * 1024 + lane;
    const uint2* pH[2][4];
    #pragma unroll
    for (int p = 0; p < 2; ++p)
        #pragma unroll
        for (int n = 0; n < 4; ++n)
            pH[p][n] = g_Bh + (p * 32 + bg * 4 + n) * 1024 + lane;

    float acc[2][4][4];
    #pragma unroll
    for (int m = 0; m < 2; ++m)
        #pragma unroll
        for (int n = 0; n < 4; ++n)
            #pragma unroll
            for (int e = 0; e < 4; ++e) acc[m][n][e] = 0.0f;

    uint4 Ab[2][2][2];
    uint2 Hb[2][2][4];
    #pragma unroll
    for (int p = 0; p < 2; ++p) {
        #pragma unroll
        for (int m = 0; m < 2; ++m) Ab[0][p][m] = pA[p][m][0];
        #pragma unroll
        for (int n = 0; n < 4; ++n) Hb[0][p][n] = pH[p][n][0];
    }

    #pragma unroll 8
    for (int ks = 0; ks < 32; ++ks) {
        const int cur = ks & 1, nxt = cur ^ 1;
        const int ksn = (ks < 31) ? ks + 1 : 31;
        #pragma unroll
        for (int p = 0; p < 2; ++p) {
            #pragma unroll
            for (int m = 0; m < 2; ++m) Ab[nxt][p][m] = pA[p][m][ksn * 32];
            #pragma unroll
            for (int n = 0; n < 4; ++n) Hb[nxt][p][n] = pH[p][n][ksn * 32];
        }
        #pragma unroll
        for (int n = 0; n < 4; ++n)
            #pragma unroll
            for (int m = 0; m < 2; ++m) {
                MMA(acc[m][n], Ab[cur][0][m], Hb[cur][0][n]);
                MMA(acc[m][n], Ab[cur][0][m], Hb[cur][1][n]);
                MMA(acc[m][n], Ab[cur][1][m], Hb[cur][0][n]);
            }
    }

    const int r = lane >> 2, c = lane & 3;
    #pragma unroll
    for (int m = 0; m < 2; ++m) {
        const int g0 = gt * 256 + w * 32 + m * 16 + r;
        #pragma unroll
        for (int e2 = 0; e2 < 2; ++e2) {
            const int g = g0 + e2 * 8;
            const bool gok = (g < GENES);
            const float bb2 = gok ? __ldg(b2 + g) : 0.0f;
            const float th  = gok ? __expf(__ldg(lth + g)) : 1.0f;
            #pragma unroll
            for (int n = 0; n < 4; ++n)
                #pragma unroll
                for (int e1 = 0; e1 < 2; ++e1) {
                    const int bb = bg * 32 + n * 8 + 2 * c + e1;
                    const float x = acc[m][n][e2 * 2 + e1] + bb2;
                    g_sc[bb * 4096 + g] = gok ? sc_from(x, th) : 0.0f;
                }
        }
    }
}

// ---- main: fp16 MMA, 2 MMAs per (m,n) tile (A 2-term, B 1-term) ----
__global__ void __launch_bounds__(256, 2)
mma_main()
{
    extern __shared__ float sU[];
    const int tid = threadIdx.x, w = tid >> 5, lane = tid & 31;
    const int b = blockIdx.x, tile = blockIdx.y;

    const uint4* pA[2][2];
    #pragma unroll
    for (int p = 0; p < 2; ++p)
        #pragma unroll
        for (int m = 0; m < 2; ++m)
            pA[p][m] = g_A + (p * 256 + tile * 16 + w * 2 + m) * 1024 + lane;
    const uint2* pB = g_B + (size_t)b * 4096 + lane;

    float acc[2][4][4];
    #pragma unroll
    for (int m = 0; m < 2; ++m)
        #pragma unroll
        for (int n = 0; n < 4; ++n)
            #pragma unroll
            for (int e = 0; e < 4; ++e) acc[m][n][e] = 0.0f;

    uint4 Ab[2][2][2];          // [stage][prec][m]
    uint2 Bb[2][4];             // [stage][n]
    #pragma unroll
    for (int p = 0; p < 2; ++p)
        #pragma unroll
        for (int m = 0; m < 2; ++m) Ab[0][p][m] = pA[p][m][0];
    #pragma unroll
    for (int n = 0; n < 4; ++n) Bb[0][n] = pB[n * 32];

    #pragma unroll 8
    for (int ks = 0; ks < 32; ++ks) {
        const int cur = ks & 1, nxt = cur ^ 1;
        const int ksn = (ks < 31) ? ks + 1 : 31;
        #pragma unroll
        for (int p = 0; p < 2; ++p)
            #pragma unroll
            for (int m = 0; m < 2; ++m) Ab[nxt][p][m] = pA[p][m][ksn * 32];
        #pragma unroll
        for (int n = 0; n < 4; ++n) Bb[nxt][n] = pB[ksn * 128 + n * 32];

        #pragma unroll
        for (int n = 0; n < 4; ++n)
            #pragma unroll
            for (int m = 0; m < 2; ++m) {
                MMA(acc[m][n], Ab[cur][0][m], Bb[cur][n]);
                MMA(acc[m][n], Ab[cur][1][m], Bb[cur][n]);
            }
    }

    // epilogue: U = sc * V into smem
    const int r = lane >> 2, c2 = (lane & 3) * 2;
    const float* scb = g_sc + b * 4096 + tile * 256 + w * 32;
    #pragma unroll
    for (int m = 0; m < 2; ++m) {
        const float sc0 = __ldg(scb + m * 16 + r);
        const float sc1 = __ldg(scb + m * 16 + r + 8);
        float* u0 = sU + (w * 32 + m * 16 + r) * USTR;
        float* u1 = u0 + 8 * USTR;
        #pragma unroll
        for (int n = 0; n < 4; ++n) {
            *reinterpret_cast<float2*>(u0 + n * 8 + c2) =
                make_float2(acc[m][n][0] * sc0, acc[m][n][1] * sc0);
            *reinterpret_cast<float2*>(u1 + n * 8 + c2) =
                make_float2(acc[m][n][2] * sc1, acc[m][n][3] * sc1);
        }
    }
    __syncthreads();

    // SYRK: Gram partial = U^T U
    const int ti = tid & 15, tj = tid >> 4;
    {
        const float* pa = sU + 2 * ti;
        const float* pq = sU + 2 * tj;
        unsigned long long ga0 = 0ULL, ga1 = 0ULL;
        #pragma unroll 4
        for (int rI = 0; rI < 256; ++rI) {
            const unsigned long long av =
                *reinterpret_cast<const unsigned long long*>(pa + rI * USTR);
            const unsigned long long bv =
                *reinterpret_cast<const unsigned long long*>(pq + rI * USTR);
            unsigned alo, ahi;
            asm("mov.b64 {%0,%1}, %2;" : "=r"(alo), "=r"(ahi) : "l"(av));
            unsigned long long ad0, ad1;
            asm("mov.b64 %0, {%1,%1};" : "=l"(ad0) : "r"(alo));
            asm("mov.b64 %0, {%1,%1};" : "=l"(ad1) : "r"(ahi));
            FMA2(ga0, ad0, bv);
            FMA2(ga1, ad1, bv);
        }
        float* dst = g_gramPart + ((size_t)tile * BATCH + b) * 1024;
        unsigned l0, h0, l1, h1;
        asm("mov.b64 {%0,%1}, %2;" : "=r"(l0), "=r"(h0) : "l"(ga0));
        asm("mov.b64 {%0,%1}, %2;" : "=r"(l1), "=r"(h1) : "l"(ga1));
        dst[(2*ti)   * 32 + 2*tj    ] = __uint_as_float(l0);
        dst[(2*ti)   * 32 + 2*tj + 1] = __uint_as_float(h0);
        dst[(2*ti+1) * 32 + 2*tj    ] = __uint_as_float(l1);
        dst[(2*ti+1) * 32 + 2*tj + 1] = __uint_as_float(h1);
    }
}

__global__ void __launch_bounds__(256)
loss_per_b_kernel()
{
    const int b = blockIdx.x, t = threadIdx.x;
    float accl = 0.0f;
    #pragma unroll
    for (int rr = 0; rr < 4; ++rr) {
        const int ij = t + rr * 256;
        float s = 0.0f;
        for (int cc = 0; cc < NTIL; ++cc)
            s += g_gramPart[((size_t)cc * BATCH + b) * 1024 + ij];
        if (ij % 33 == 0) s -= 1.0f;
        accl = fmaf(s, s, accl);
    }
    __shared__ float red[256];
    red[t] = accl;
    __syncthreads();
    for (int o = 128; o > 0; o >>= 1) {
        if (t < o) red[t] += red[t + o];
        __syncthreads();
    }
    if (t == 0) g_lossb[b] = red[0];
}

__global__ void __launch_bounds__(256)
final_reduce_kernel(float* __restrict__ out)
{
    const int t = threadIdx.x;
    __shared__ float red[256];
    red[t] = g_lossb[t];
    __syncthreads();
    for (int o = 128; o > 0; o >>= 1) {
        if (t < o) red[t] += red[t + o];
        __syncthreads();
    }
    if (t == 0) out[0] = red[0] * (1.0f / (float)BATCH);
}

extern "C" void kernel_launch(void* const* d_in, const int* in_sizes, int n_in,
                              void* d_out, int out_size)
{
    const float* z   = (const float*)d_in[0];
    const float* W1  = (const float*)d_in[1];
    const float* b1  = (const float*)d_in[2];
    const float* W2  = (const float*)d_in[3];
    const float* b2  = (const float*)d_in[4];
    const float* lth = (const float*)d_in[5];

    pre1_kernel<<<BATCH, 256>>>(z, W1, b1);
    prepA_kernel<<<256, 256>>>(W2);

    const int smBsz = (DLAT * HID + 2 * HID) * sizeof(float);   // 69,632
    cudaFuncSetAttribute(prepB_kernel, cudaFuncAttributeMaxDynamicSharedMemorySize, smBsz);
    prepB_kernel<<<BATCH / 2, 256, smBsz>>>(W1);
    prepH_kernel<<<dim3(32, 4), 256>>>();
    sc_mma_kernel<<<dim3(16, 8), 256>>>(b2, lth);

    const int smU = 256 * USTR * sizeof(float);
    cudaFuncSetAttribute(mma_main, cudaFuncAttributeMaxDynamicSharedMemorySize, smU);
    mma_main<<<dim3(BATCH, NTIL), 256, smU>>>();

    loss_per_b_kernel<<<BATCH, 256>>>();
    final_reduce_kernel<<<1, 256>>>((float*)d_out);
}